// round 3
// baseline (speedup 1.0000x reference)
#include <cuda_runtime.h>
#include <math.h>

#define HH 16
#define SS 4096
#define DD 64
#define SCALE 0.125f

static __device__ __forceinline__ float neg_inf() {
    return __int_as_float(0xff800000);
}

// ---------------------------------------------------------------------------
// K1: scores[h][q][k] = mask ? -inf : (Q . K) * scale
// Block tile: 128 q-rows x 64 k-cols. 256 threads, 8x4 micro-tile per thread.
// smem: Qs[d][qrow] (64x128), Ks[d][kcol] (64x64)  -> exactly 48KB
// ---------------------------------------------------------------------------
__global__ __launch_bounds__(256) void scores_kernel(
    const float* __restrict__ q, const float* __restrict__ k,
    const int* __restrict__ mask, float* __restrict__ attn)
{
    __shared__ float Qs[DD][128];
    __shared__ float Ks[DD][64];

    const int h  = blockIdx.z;
    const int q0 = blockIdx.y * 128;
    const int k0 = blockIdx.x * 64;
    const int tid = threadIdx.x;

    const float* qb = q + ((size_t)h * SS + q0) * DD;
    const float* kb = k + ((size_t)h * SS + k0) * DD;

    // Load Q tile (128 rows x 64 d), transposed into Qs[d][row]
#pragma unroll
    for (int i = 0; i < 8; i++) {
        int linear = tid + i * 256;        // 0..2047
        int row = linear >> 4;             // 16 float4 per row
        int dg  = (linear & 15) * 4;
        float4 t = *(const float4*)(qb + (size_t)row * DD + dg);
        Qs[dg + 0][row] = t.x; Qs[dg + 1][row] = t.y;
        Qs[dg + 2][row] = t.z; Qs[dg + 3][row] = t.w;
    }
    // Load K tile (64 rows x 64 d), transposed into Ks[d][col]
#pragma unroll
    for (int i = 0; i < 4; i++) {
        int linear = tid + i * 256;        // 0..1023
        int row = linear >> 4;
        int dg  = (linear & 15) * 4;
        float4 t = *(const float4*)(kb + (size_t)row * DD + dg);
        Ks[dg + 0][row] = t.x; Ks[dg + 1][row] = t.y;
        Ks[dg + 2][row] = t.z; Ks[dg + 3][row] = t.w;
    }
    __syncthreads();

    const int tx = tid & 15;   // col group: cols tx*4 .. tx*4+3
    const int ty = tid >> 4;   // row group: rows ty*4..+3 and 64+ty*4..+3

    float acc[8][4];
#pragma unroll
    for (int r = 0; r < 8; r++)
#pragma unroll
        for (int c = 0; c < 4; c++) acc[r][c] = 0.f;

#pragma unroll 8
    for (int d = 0; d < DD; d++) {
        float4 a0 = *(float4*)&Qs[d][ty * 4];
        float4 a1 = *(float4*)&Qs[d][64 + ty * 4];
        float4 b  = *(float4*)&Ks[d][tx * 4];
        float av[8] = {a0.x, a0.y, a0.z, a0.w, a1.x, a1.y, a1.z, a1.w};
        float bv[4] = {b.x, b.y, b.z, b.w};
#pragma unroll
        for (int r = 0; r < 8; r++)
#pragma unroll
            for (int c = 0; c < 4; c++) acc[r][c] += av[r] * bv[c];
    }

    // Epilogue: scale, mask (int32 per element!), write
    const int colg0 = k0 + tx * 4;
#pragma unroll
    for (int r = 0; r < 8; r++) {
        int rowl = (r < 4) ? (ty * 4 + r) : (64 + ty * 4 + (r - 4));
        int rowg = q0 + rowl;
        int4 mv = *(const int4*)(mask + (size_t)rowg * SS + colg0);
        float4 o;
        o.x = mv.x ? neg_inf() : acc[r][0] * SCALE;
        o.y = mv.y ? neg_inf() : acc[r][1] * SCALE;
        o.z = mv.z ? neg_inf() : acc[r][2] * SCALE;
        o.w = mv.w ? neg_inf() : acc[r][3] * SCALE;
        *(float4*)(attn + ((size_t)h * SS + rowg) * SS + colg0) = o;
    }
}

// ---------------------------------------------------------------------------
// K2: in-place row softmax on attn. One block (256 thr) per row of 4096.
// ---------------------------------------------------------------------------
__global__ __launch_bounds__(256) void softmax_kernel(float* __restrict__ attn)
{
    const int b = blockIdx.x;
    const int h = b >> 12;
    const int row = b & 4095;
    float* p = attn + ((size_t)h * SS + row) * SS;
    const int tid = threadIdx.x;
    const int lane = tid & 31, warp = tid >> 5;

    __shared__ float sred[8];
    __shared__ float bcast;

    float4 v[4];
    float m = neg_inf();
#pragma unroll
    for (int i = 0; i < 4; i++) {
        v[i] = ((const float4*)p)[tid + i * 256];
        m = fmaxf(m, fmaxf(fmaxf(v[i].x, v[i].y), fmaxf(v[i].z, v[i].w)));
    }
#pragma unroll
    for (int o = 16; o > 0; o >>= 1)
        m = fmaxf(m, __shfl_xor_sync(0xffffffffu, m, o));
    if (lane == 0) sred[warp] = m;
    __syncthreads();
    if (tid == 0) {
        float t = sred[0];
#pragma unroll
        for (int i = 1; i < 8; i++) t = fmaxf(t, sred[i]);
        bcast = t;
    }
    __syncthreads();
    m = bcast;

    float sum = 0.f;
#pragma unroll
    for (int i = 0; i < 4; i++) {
        v[i].x = __expf(v[i].x - m);
        v[i].y = __expf(v[i].y - m);
        v[i].z = __expf(v[i].z - m);
        v[i].w = __expf(v[i].w - m);
        sum += (v[i].x + v[i].y) + (v[i].z + v[i].w);
    }
#pragma unroll
    for (int o = 16; o > 0; o >>= 1)
        sum += __shfl_xor_sync(0xffffffffu, sum, o);
    __syncthreads();   // protect sred reuse
    if (lane == 0) sred[warp] = sum;
    __syncthreads();
    if (tid == 0) {
        float t = 0.f;
#pragma unroll
        for (int i = 0; i < 8; i++) t += sred[i];
        bcast = t;
    }
    __syncthreads();
    const float inv = 1.0f / bcast;

#pragma unroll
    for (int i = 0; i < 4; i++) {
        v[i].x *= inv; v[i].y *= inv; v[i].z *= inv; v[i].w *= inv;
        ((float4*)p)[tid + i * 256] = v[i];
    }
}

// ---------------------------------------------------------------------------
// K3: out[h][q][d] = sum_k attn[h][q][k] * v[h][k][d]
// Block tile: 128 q-rows x 64 d-cols, k-chunks of 64.
// smem: As[k][row] (64x128), Vs[k][d] (64x64)  -> 48KB
// ---------------------------------------------------------------------------
__global__ __launch_bounds__(256) void pv_kernel(
    const float* __restrict__ attn, const float* __restrict__ v,
    float* __restrict__ out)
{
    __shared__ float As[64][128];
    __shared__ float Vs[64][DD];

    const int h  = blockIdx.z;
    const int q0 = blockIdx.y * 128;
    const int tid = threadIdx.x;
    const int tx = tid & 15;
    const int ty = tid >> 4;

    const float* ab = attn + ((size_t)h * SS + q0) * SS;
    const float* vb = v + (size_t)h * SS * DD;

    float acc[8][4];
#pragma unroll
    for (int r = 0; r < 8; r++)
#pragma unroll
        for (int c = 0; c < 4; c++) acc[r][c] = 0.f;

    for (int kc = 0; kc < SS; kc += 64) {
        // attn tile: 128 rows x 64 k, transposed into As[k][row]
#pragma unroll
        for (int i = 0; i < 8; i++) {
            int linear = tid + i * 256;
            int row = linear >> 4;
            int kg  = (linear & 15) * 4;
            float4 t = *(const float4*)(ab + (size_t)row * SS + kc + kg);
            As[kg + 0][row] = t.x; As[kg + 1][row] = t.y;
            As[kg + 2][row] = t.z; As[kg + 3][row] = t.w;
        }
        // V tile: 64 k x 64 d, natural layout
#pragma unroll
        for (int i = 0; i < 4; i++) {
            int linear = tid + i * 256;
            int kr = linear >> 4;
            int dg = (linear & 15) * 4;
            *(float4*)&Vs[kr][dg] =
                *(const float4*)(vb + (size_t)(kc + kr) * DD + dg);
        }
        __syncthreads();

#pragma unroll 8
        for (int kk = 0; kk < 64; kk++) {
            float4 a0 = *(float4*)&As[kk][ty * 4];
            float4 a1 = *(float4*)&As[kk][64 + ty * 4];
            float4 b  = *(float4*)&Vs[kk][tx * 4];
            float av[8] = {a0.x, a0.y, a0.z, a0.w, a1.x, a1.y, a1.z, a1.w};
            float bv[4] = {b.x, b.y, b.z, b.w};
#pragma unroll
            for (int r = 0; r < 8; r++)
#pragma unroll
                for (int c = 0; c < 4; c++) acc[r][c] += av[r] * bv[c];
        }
        __syncthreads();
    }

#pragma unroll
    for (int r = 0; r < 8; r++) {
        int rowl = (r < 4) ? (ty * 4 + r) : (64 + ty * 4 + (r - 4));
        int rowg = q0 + rowl;
        float4 o = make_float4(acc[r][0], acc[r][1], acc[r][2], acc[r][3]);
        *(float4*)(out + ((size_t)h * SS + rowg) * DD + tx * 4) = o;
    }
}

// ---------------------------------------------------------------------------
extern "C" void kernel_launch(void* const* d_in, const int* in_sizes, int n_in,
                              void* d_out, int out_size)
{
    const float* q = (const float*)d_in[0];
    const float* k = (const float*)d_in[1];
    const float* v = (const float*)d_in[2];
    const int* mask = (const int*)d_in[3];

    float* out  = (float*)d_out;                         // [16,4096,64]
    float* attn = out + (size_t)HH * SS * DD;            // [16,4096,4096]

    dim3 g1(SS / 64, SS / 128, HH);
    scores_kernel<<<g1, 256>>>(q, k, mask, attn);

    softmax_kernel<<<HH * SS, 256>>>(attn);

    dim3 g3(1, SS / 128, HH);
    pv_kernel<<<g3, 256>>>(attn, v, out);
}

// round 5
// speedup vs baseline: 1.8973x; 1.8973x over previous
#include <cuda_runtime.h>
#include <cuda_bf16.h>
#include <stdint.h>

#define HH 16
#define SS 4096
#define DD 64
#define NEGINF __int_as_float(0xff800000)

__device__ __align__(16) __nv_bfloat16 g_qhi[HH * SS * DD];
__device__ __align__(16) __nv_bfloat16 g_qlo[HH * SS * DD];
__device__ __align__(16) __nv_bfloat16 g_khi[HH * SS * DD];
__device__ __align__(16) __nv_bfloat16 g_klo[HH * SS * DD];
__device__ __align__(16) __nv_bfloat16 g_vthi[HH * DD * SS];
__device__ __align__(16) __nv_bfloat16 g_vtlo[HH * DD * SS];

static __device__ __forceinline__ uint32_t smem_u32(const void* p) {
    uint32_t a;
    asm("{ .reg .u64 t; cvta.to.shared.u64 t, %1; cvt.u32.u64 %0, t; }" : "=r"(a) : "l"(p));
    return a;
}
static __device__ __forceinline__ void ldsm4(uint32_t* r, uint32_t a) {
    asm volatile("ldmatrix.sync.aligned.m8n8.x4.shared.b16 {%0,%1,%2,%3}, [%4];"
        : "=r"(r[0]), "=r"(r[1]), "=r"(r[2]), "=r"(r[3]) : "r"(a));
}
static __device__ __forceinline__ void mma16816(float* c, const uint32_t* a,
                                                uint32_t b0, uint32_t b1) {
    asm volatile("mma.sync.aligned.m16n8k16.row.col.f32.bf16.bf16.f32 "
        "{%0,%1,%2,%3}, {%4,%5,%6,%7}, {%8,%9}, {%0,%1,%2,%3};"
        : "+f"(c[0]), "+f"(c[1]), "+f"(c[2]), "+f"(c[3])
        : "r"(a[0]), "r"(a[1]), "r"(a[2]), "r"(a[3]), "r"(b0), "r"(b1));
}

// ===================== converts =====================
__global__ __launch_bounds__(256) void convert_qk(const float* __restrict__ q,
                                                  const float* __restrict__ k) {
    int i = blockIdx.x * 256 + threadIdx.x;
    float fq = q[i] * 0.125f;
    __nv_bfloat16 qh = __float2bfloat16(fq);
    g_qhi[i] = qh; g_qlo[i] = __float2bfloat16(fq - __bfloat162float(qh));
    float fk = k[i];
    __nv_bfloat16 kh = __float2bfloat16(fk);
    g_khi[i] = kh; g_klo[i] = __float2bfloat16(fk - __bfloat162float(kh));
}
__global__ __launch_bounds__(256) void convert_v(const float* __restrict__ v) {
    __shared__ __nv_bfloat16 th[64][65], tl[64][65];
    const int h = blockIdx.y, s0 = blockIdx.x * 64, tid = threadIdx.x;
#pragma unroll
    for (int j = 0; j < 16; j++) {
        int i = tid + j * 256, sr = i >> 6, d = i & 63;
        float f = v[((size_t)(h * SS + s0 + sr)) * DD + d];
        __nv_bfloat16 hi = __float2bfloat16(f);
        th[sr][d] = hi; tl[sr][d] = __float2bfloat16(f - __bfloat162float(hi));
    }
    __syncthreads();
#pragma unroll
    for (int j = 0; j < 16; j++) {
        int i = tid + j * 256, d = i >> 6, sr = i & 63;
        size_t o = ((size_t)(h * DD + d)) * SS + s0 + sr;
        g_vthi[o] = th[sr][d]; g_vtlo[o] = tl[sr][d];
    }
}

// ===================== K1: scores via HMMA =====================
// smem bf16 tiles, row stride 144B (72 bf16) -> conflict-free ldmatrix
#define K1_QHI 0
#define K1_QLO 18432
#define K1_KHI 36864
#define K1_KLO 55296
#define K1_MSK 73728
#define K1_BYTES (K1_MSK + 128 * 132)

__global__ __launch_bounds__(256) void scores_mma(const int* __restrict__ mask,
                                                  float* __restrict__ attn) {
    extern __shared__ char sm[];
    const uint32_t sb = smem_u32(sm);
    const int h = blockIdx.x, q0 = blockIdx.y * 128, tid = threadIdx.x;
    const int wid = tid >> 5, lane = tid & 31;

    {   // Q tile (128 rows x 64 bf16), hi+lo
        const __nv_bfloat16* qh = g_qhi + ((size_t)(h * SS + q0)) * DD;
        const __nv_bfloat16* ql = g_qlo + ((size_t)(h * SS + q0)) * DD;
#pragma unroll
        for (int j = 0; j < 4; j++) {
            int i = tid + j * 256, row = i >> 3, u = i & 7;
            *(uint4*)(sm + K1_QHI + row * 144 + u * 16) = *(const uint4*)(qh + row * DD + u * 8);
            *(uint4*)(sm + K1_QLO + row * 144 + u * 16) = *(const uint4*)(ql + row * DD + u * 8);
        }
    }
    const int warp_m = wid & 3, warp_n = wid >> 2;
    const int lr = lane & 15, lc = lane >> 4;
    const uint32_t aoff = sb + K1_QHI + (uint32_t)(warp_m * 32 + lr) * 144 + lc * 16;
    const uint32_t boff = sb + K1_KHI + (uint32_t)(warp_n * 64 + lr) * 144 + lc * 16;

    for (int kt = 0; kt < 32; kt++) {
        {   // K tile + mask tile
            const __nv_bfloat16* kh = g_khi + ((size_t)(h * SS + kt * 128)) * DD;
            const __nv_bfloat16* kl = g_klo + ((size_t)(h * SS + kt * 128)) * DD;
#pragma unroll
            for (int j = 0; j < 4; j++) {
                int i = tid + j * 256, row = i >> 3, u = i & 7;
                *(uint4*)(sm + K1_KHI + row * 144 + u * 16) = *(const uint4*)(kh + row * DD + u * 8);
                *(uint4*)(sm + K1_KLO + row * 144 + u * 16) = *(const uint4*)(kl + row * DD + u * 8);
            }
            unsigned char* mp = (unsigned char*)(sm + K1_MSK);
#pragma unroll
            for (int j = 0; j < 16; j++) {
                int i = tid + j * 256, row = i >> 5, c4 = i & 31;
                int4 m = *(const int4*)(mask + (size_t)(q0 + row) * SS + kt * 128 + c4 * 4);
                uchar4 b;
                b.x = m.x ? 1 : 0; b.y = m.y ? 1 : 0; b.z = m.z ? 1 : 0; b.w = m.w ? 1 : 0;
                *(uchar4*)(mp + row * 132 + c4 * 4) = b;
            }
        }
        __syncthreads();

        float acc[2][8][4];
#pragma unroll
        for (int mi = 0; mi < 2; mi++)
#pragma unroll
            for (int n = 0; n < 8; n++)
#pragma unroll
                for (int c = 0; c < 4; c++) acc[mi][n][c] = 0.f;

#pragma unroll
        for (int ks = 0; ks < 4; ks++) {
            uint32_t ah[2][4], al[2][4];
            ldsm4(ah[0], aoff + ks * 32);
            ldsm4(ah[1], aoff + ks * 32 + 16 * 144);
            ldsm4(al[0], aoff + 18432 + ks * 32);
            ldsm4(al[1], aoff + 18432 + ks * 32 + 16 * 144);
#pragma unroll
            for (int ng = 0; ng < 4; ng++) {
                uint32_t bh[4], bl[4];
                ldsm4(bh, boff + ks * 32 + ng * 16 * 144);
                ldsm4(bl, boff + 18432 + ks * 32 + ng * 16 * 144);
#pragma unroll
                for (int mi = 0; mi < 2; mi++) {
                    mma16816(acc[mi][2 * ng], ah[mi], bh[0], bh[2]);
                    mma16816(acc[mi][2 * ng + 1], ah[mi], bh[1], bh[3]);
                    mma16816(acc[mi][2 * ng], ah[mi], bl[0], bl[2]);
                    mma16816(acc[mi][2 * ng + 1], ah[mi], bl[1], bl[3]);
                    mma16816(acc[mi][2 * ng], al[mi], bh[0], bh[2]);
                    mma16816(acc[mi][2 * ng + 1], al[mi], bh[1], bh[3]);
                }
            }
        }
        // epilogue: mask + store
        const unsigned char* mp = (const unsigned char*)(sm + K1_MSK);
#pragma unroll
        for (int mi = 0; mi < 2; mi++) {
            int rowl = warp_m * 32 + mi * 16 + (lane >> 2);
#pragma unroll
            for (int ng = 0; ng < 8; ng++) {
                int coll = warp_n * 64 + ng * 8 + (lane & 3) * 2;
                uchar2 m0 = *(const uchar2*)(mp + rowl * 132 + coll);
                uchar2 m1 = *(const uchar2*)(mp + (rowl + 8) * 132 + coll);
                float2 v0, v1;
                v0.x = m0.x ? NEGINF : acc[mi][ng][0];
                v0.y = m0.y ? NEGINF : acc[mi][ng][1];
                v1.x = m1.x ? NEGINF : acc[mi][ng][2];
                v1.y = m1.y ? NEGINF : acc[mi][ng][3];
                float* op = attn + ((size_t)(h * SS + q0 + rowl)) * SS + kt * 128 + coll;
                *(float2*)op = v0;
                *(float2*)(op + 8 * SS) = v1;
            }
        }
        __syncthreads();
    }
}

// ===================== K2: softmax (in-place) =====================
__global__ __launch_bounds__(256) void softmax_kernel(float* __restrict__ attn) {
    const int b = blockIdx.x, h = b >> 12, row = b & 4095;
    float* p = attn + ((size_t)h * SS + row) * SS;
    const int tid = threadIdx.x, lane = tid & 31, warp = tid >> 5;
    __shared__ float sred[8];
    __shared__ float bcast;
    float4 v[4];
    float m = NEGINF;
#pragma unroll
    for (int i = 0; i < 4; i++) {
        v[i] = ((const float4*)p)[tid + i * 256];
        m = fmaxf(m, fmaxf(fmaxf(v[i].x, v[i].y), fmaxf(v[i].z, v[i].w)));
    }
#pragma unroll
    for (int o = 16; o > 0; o >>= 1) m = fmaxf(m, __shfl_xor_sync(~0u, m, o));
    if (lane == 0) sred[warp] = m;
    __syncthreads();
    if (tid == 0) {
        float t = sred[0];
#pragma unroll
        for (int i = 1; i < 8; i++) t = fmaxf(t, sred[i]);
        bcast = t;
    }
    __syncthreads();
    m = bcast;
    float sum = 0.f;
#pragma unroll
    for (int i = 0; i < 4; i++) {
        v[i].x = __expf(v[i].x - m); v[i].y = __expf(v[i].y - m);
        v[i].z = __expf(v[i].z - m); v[i].w = __expf(v[i].w - m);
        sum += (v[i].x + v[i].y) + (v[i].z + v[i].w);
    }
#pragma unroll
    for (int o = 16; o > 0; o >>= 1) sum += __shfl_xor_sync(~0u, sum, o);
    __syncthreads();
    if (lane == 0) sred[warp] = sum;
    __syncthreads();
    if (tid == 0) {
        float t = 0.f;
#pragma unroll
        for (int i = 0; i < 8; i++) t += sred[i];
        bcast = t;
    }
    __syncthreads();
    const float inv = 1.0f / bcast;
#pragma unroll
    for (int i = 0; i < 4; i++) {
        v[i].x *= inv; v[i].y *= inv; v[i].z *= inv; v[i].w *= inv;
        ((float4*)p)[tid + i * 256] = v[i];
    }
}

// ===================== K3: PV via HMMA =====================
// P smem [128 q][128 k] bf16, stride 272B. V smem [64 d][128 k] bf16, stride 272B.
#define K3_PHI 0
#define K3_PLO 34816
#define K3_VHI 69632
#define K3_VLO (K3_VHI + 17408)
#define K3_BYTES (K3_VLO + 17408)

static __device__ __forceinline__ uint32_t pack2(__nv_bfloat16 a, __nv_bfloat16 b) {
    return ((uint32_t)__bfloat16_as_ushort(b) << 16) | (uint32_t)__bfloat16_as_ushort(a);
}

__global__ __launch_bounds__(256) void pv_mma(const float* __restrict__ attn,
                                              float* __restrict__ out) {
    extern __shared__ char sm[];
    const uint32_t sb = smem_u32(sm);
    const int h = blockIdx.x, q0 = blockIdx.y * 128, tid = threadIdx.x;
    const int wid = tid >> 5, lane = tid & 31;
    const int lr = lane & 15, lc = lane >> 4;

    float acc[8][4];
#pragma unroll
    for (int n = 0; n < 8; n++)
#pragma unroll
        for (int c = 0; c < 4; c++) acc[n][c] = 0.f;

    const uint32_t aoff = sb + K3_PHI + (uint32_t)(wid * 16 + lr) * 272 + lc * 16;
    const uint32_t boff = sb + K3_VHI + (uint32_t)lr * 272 + lc * 16;

    for (int kt = 0; kt < 32; kt++) {
        const int k0 = kt * 128;
#pragma unroll
        for (int j = 0; j < 16; j++) {  // P fp32 -> bf16 hi/lo split
            int i = tid + j * 256, row = i >> 5, c4 = i & 31;
            float4 p = *(const float4*)(attn + ((size_t)(h * SS + q0 + row)) * SS + k0 + c4 * 4);
            __nv_bfloat16 hx = __float2bfloat16(p.x), hy = __float2bfloat16(p.y);
            __nv_bfloat16 hz = __float2bfloat16(p.z), hw = __float2bfloat16(p.w);
            uint2 hv, lv;
            hv.x = pack2(hx, hy); hv.y = pack2(hz, hw);
            lv.x = pack2(__float2bfloat16(p.x - __bfloat162float(hx)),
                         __float2bfloat16(p.y - __bfloat162float(hy)));
            lv.y = pack2(__float2bfloat16(p.z - __bfloat162float(hz)),
                         __float2bfloat16(p.w - __bfloat162float(hw)));
            *(uint2*)(sm + K3_PHI + row * 272 + c4 * 8) = hv;
            *(uint2*)(sm + K3_PLO + row * 272 + c4 * 8) = lv;
        }
#pragma unroll
        for (int j = 0; j < 4; j++) {  // V tiles [64 d][128 k]
            int i = tid + j * 256, d = i >> 4, u = i & 15;
            size_t go = ((size_t)(h * DD + d)) * SS + k0 + u * 8;
            *(uint4*)(sm + K3_VHI + d * 272 + u * 16) = *(const uint4*)(g_vthi + go);
            *(uint4*)(sm + K3_VLO + d * 272 + u * 16) = *(const uint4*)(g_vtlo + go);
        }
        __syncthreads();

#pragma unroll
        for (int ks = 0; ks < 8; ks++) {
            uint32_t ah[4], al[4];
            ldsm4(ah, aoff + ks * 32);
            ldsm4(al, aoff + K3_PLO + ks * 32);
#pragma unroll
            for (int ng = 0; ng < 4; ng++) {
                uint32_t bh[4], bl[4];
                ldsm4(bh, boff + ks * 32 + ng * 16 * 272);
                ldsm4(bl, boff + 17408 + ks * 32 + ng * 16 * 272);
                mma16816(acc[2 * ng], ah, bh[0], bh[2]);
                mma16816(acc[2 * ng + 1], ah, bh[1], bh[3]);
                mma16816(acc[2 * ng], ah, bl[0], bl[2]);
                mma16816(acc[2 * ng + 1], ah, bl[1], bl[3]);
                mma16816(acc[2 * ng], al, bh[0], bh[2]);
                mma16816(acc[2 * ng + 1], al, bh[1], bh[3]);
            }
        }
        __syncthreads();
    }
    // epilogue
    const int rowl = wid * 16 + (lane >> 2);
#pragma unroll
    for (int ng = 0; ng < 8; ng++) {
        int col = ng * 8 + (lane & 3) * 2;
        float* op = out + ((size_t)(h * SS + q0 + rowl)) * DD + col;
        *(float2*)op = make_float2(acc[ng][0], acc[ng][1]);
        *(float2*)(op + 8 * DD) = make_float2(acc[ng][2], acc[ng][3]);
    }
}

// ===================== launch =====================
extern "C" void kernel_launch(void* const* d_in, const int* in_sizes, int n_in,
                              void* d_out, int out_size) {
    const float* q = (const float*)d_in[0];
    const float* k = (const float*)d_in[1];
    const float* v = (const float*)d_in[2];
    const int* mask = (const int*)d_in[3];
    float* out = (float*)d_out;
    float* attn = out + (size_t)HH * SS * DD;

    cudaFuncSetAttribute(scores_mma, cudaFuncAttributeMaxDynamicSharedMemorySize, K1_BYTES);
    cudaFuncSetAttribute(pv_mma, cudaFuncAttributeMaxDynamicSharedMemorySize, K3_BYTES);

    convert_qk<<<(HH * SS * DD) / 256, 256>>>(q, k);
    convert_v<<<dim3(SS / 64, HH), 256>>>(v);
    scores_mma<<<dim3(HH, SS / 128), 256, K1_BYTES>>>(mask, attn);
    softmax_kernel<<<HH * SS, 256>>>(attn);
    pv_mma<<<dim3(HH, SS / 128), 256, K3_BYTES>>>(attn, out);
}